// round 14
// baseline (speedup 1.0000x reference)
#include <cuda_runtime.h>
#include <cuda_fp16.h>
#include <cstdint>

#define NB 32
#define NN 2000
#define NE 64000
#define ND 128
#define WCHUNK 5

// ---------------- scratch ----------------
__device__ int    g_cursor[NN];
__device__ float  g_dinv[NN];
__device__ float  g_selfn[NN];
__device__ float  g_c[NN];
__device__ int    g_rs[NN + 1];
__device__ int2   g_csr[NE];            // (src*16 [uint4 units], w packed half2)
__device__ float  g_v[NB * ND];
__device__ __half g_h1[(size_t)NB * NN * ND];  // layer-1 output, fp16 (16.4 MB)

__device__ __forceinline__ __half2 u2h2(unsigned u) { return *reinterpret_cast<__half2*>(&u); }

// ---------------- prep: count(smem) + scan + dinv/selfn/c + zero, one block ----------------
__global__ void k_scandinv(const int* __restrict__ dst) {
    __shared__ int cnt[2048];
    __shared__ int s[2048];
    int t = threadIdx.x;                 // 1024 threads
    cnt[t] = 0; cnt[t + 1024] = 0;
    __syncthreads();
    for (int e = t; e < NE; e += 1024) atomicAdd(&cnt[dst[e]], 1);
    __syncthreads();
    for (int i = t; i < NN; i += 1024) {
        float di = rsqrtf((float)(cnt[i] + 1));
        g_dinv[i]  = di;
        float sn   = di * di;
        g_selfn[i] = sn;
        g_c[i]     = sn;
        g_cursor[i] = 0;
    }
    s[t] = cnt[t]; s[t + 1024] = cnt[t + 1024];
    __syncthreads();
    for (int off = 1; off < 2048; off <<= 1) {
        int v0 = (t >= off) ? s[t - off] : 0;
        int v1 = s[t + 1024 - off];
        __syncthreads();
        s[t] += v0;
        s[t + 1024] += v1;
        __syncthreads();
    }
    if (t == 0) g_rs[0] = 0;
    if (t < NN) g_rs[t + 1] = s[t];
    if (t + 1024 < NN) g_rs[t + 1025] = s[t + 1024];
    for (int i = t; i < NB * ND; i += 1024) g_v[i] = 0.f;
}

__global__ void k_scatter(const int* __restrict__ src, const int* __restrict__ dst) {
    int e = blockIdx.x * blockDim.x + threadIdx.x;
    if (e < NE) {
        int dd = dst[e], ss = src[e];
        float w = g_dinv[ss] * g_dinv[dd];
        int p = g_rs[dd] + atomicAdd(&g_cursor[dd], 1);
        __half2 hw = __floats2half2_rn(w, w);
        g_csr[p] = make_int2(ss * 16, *reinterpret_cast<int*>(&hw));
        atomicAdd(&g_c[ss], w);
    }
}

// ---------------- GEMM1 via mma.sync (HMMA): h1 = X @ W1, fp16 in, fp32 acc ----------------
#define AS_STRIDE 132

__device__ __forceinline__ void mma16816(float* c, const uint32_t* a, const uint32_t* b) {
    asm volatile(
        "mma.sync.aligned.m16n8k16.row.col.f32.f16.f16.f32 "
        "{%0,%1,%2,%3}, {%4,%5,%6,%7}, {%8,%9}, {%0,%1,%2,%3};"
        : "+f"(c[0]), "+f"(c[1]), "+f"(c[2]), "+f"(c[3])
        : "r"(a[0]), "r"(a[1]), "r"(a[2]), "r"(a[3]), "r"(b[0]), "r"(b[1]));
}

__global__ void __launch_bounds__(256, 1)
k_gemm_mma(const float* __restrict__ X, const float* __restrict__ W1) {
    __shared__ __half As[128 * AS_STRIDE];
    __shared__ __half Bs[128 * AS_STRIDE];   // Bs[n][k] = W1[k][n]
    int tid = threadIdx.x;
    int wid = tid >> 5, lane = tid & 31;
    size_t row0 = (size_t)blockIdx.x * 128;

#pragma unroll
    for (int i = 0; i < 32; i++) {
        int idx = tid + i * 256;
        int row = idx >> 6, c2 = idx & 63;
        float2 xv = *(const float2*)(X + (row0 + row) * ND + c2 * 2);
        *(__half2*)(As + row * AS_STRIDE + c2 * 2) = __floats2half2_rn(xv.x, xv.y);
    }
#pragma unroll
    for (int i = 0; i < 64; i++) {
        int idx = tid + i * 256;
        int n = idx & 127, k = idx >> 7;
        Bs[n * AS_STRIDE + k] = __float2half(W1[idx]);
    }
    __syncthreads();

    int wr = (wid & 3) * 32;
    int wc = (wid >> 2) * 64;
    int grp = lane >> 2;
    int tig = lane & 3;

    float acc[2][8][4];
#pragma unroll
    for (int mt = 0; mt < 2; mt++)
#pragma unroll
        for (int nt = 0; nt < 8; nt++)
#pragma unroll
            for (int q = 0; q < 4; q++) acc[mt][nt][q] = 0.f;

#pragma unroll
    for (int kc = 0; kc < 8; kc++) {
        int k0 = kc * 16;
        uint32_t a[2][4];
#pragma unroll
        for (int mt = 0; mt < 2; mt++) {
            const __half* base = As + (wr + mt * 16) * AS_STRIDE + k0;
            a[mt][0] = *(const uint32_t*)(base + grp * AS_STRIDE + tig * 2);
            a[mt][1] = *(const uint32_t*)(base + (grp + 8) * AS_STRIDE + tig * 2);
            a[mt][2] = *(const uint32_t*)(base + grp * AS_STRIDE + tig * 2 + 8);
            a[mt][3] = *(const uint32_t*)(base + (grp + 8) * AS_STRIDE + tig * 2 + 8);
        }
#pragma unroll
        for (int nt = 0; nt < 8; nt++) {
            uint32_t b[2];
            const __half* bb = Bs + (wc + nt * 8 + grp) * AS_STRIDE + k0;
            b[0] = *(const uint32_t*)(bb + tig * 2);
            b[1] = *(const uint32_t*)(bb + tig * 2 + 8);
            mma16816(acc[0][nt], a[0], b);
            mma16816(acc[1][nt], a[1], b);
        }
    }

#pragma unroll
    for (int mt = 0; mt < 2; mt++) {
        size_t r0 = row0 + wr + mt * 16 + grp;
#pragma unroll
        for (int nt = 0; nt < 8; nt++) {
            int col = wc + nt * 8 + tig * 2;
            __half2 lo = __floats2half2_rn(acc[mt][nt][0], acc[mt][nt][1]);
            __half2 hi = __floats2half2_rn(acc[mt][nt][2], acc[mt][nt][3]);
            *(__half2*)(g_h1 + r0 * ND + col)       = lo;
            *(__half2*)(g_h1 + (r0 + 8) * ND + col) = hi;
        }
    }
}

// ---------------- agg: 2 edges/warp-iter (parity groups), unroll 4, HFMA2 ----------------
// block = 128 threads (4 warps); each warp: WCHUNK dsts; 16 lanes cover 128 dims
__global__ void __launch_bounds__(128)
k_agg(const float* __restrict__ b1) {
    int warp = threadIdx.x >> 5, lane = threadIdx.x & 31;
    int hf = lane >> 4;                   // edge-parity group
    int sl = lane & 15;                   // dims 8*sl .. 8*sl+7
    int b = blockIdx.y;
    int dst0 = (blockIdx.x * 4 + warp) * WCHUNK;
    int dst1 = min(dst0 + WCHUNK, NN);
    const uint4* __restrict__ hb = (const uint4*)(g_h1 + (size_t)b * NN * ND);

    float4 vacc0 = make_float4(0.f, 0.f, 0.f, 0.f);
    float4 vacc1 = make_float4(0.f, 0.f, 0.f, 0.f);

    for (int dst = dst0; dst < dst1; ++dst) {
        int s = g_rs[dst], e = g_rs[dst + 1];
        __half2 a0 = __floats2half2_rn(0.f, 0.f), a1 = a0, a2 = a0, a3 = a0;
        int i = s + hf;
        // unroll 4: group handles edges i, i+2, i+4, i+6 -> 4 LDG.128 in flight
        for (; i + 6 < e; i += 8) {
            int2 eA = g_csr[i],     eB = g_csr[i + 2];
            int2 eC = g_csr[i + 4], eD = g_csr[i + 6];
            uint4 hA = hb[eA.x + sl];
            uint4 hB = hb[eB.x + sl];
            uint4 hC = hb[eC.x + sl];
            uint4 hD = hb[eD.x + sl];
            __half2 wA = u2h2((unsigned)eA.y), wB = u2h2((unsigned)eB.y);
            __half2 wC = u2h2((unsigned)eC.y), wD = u2h2((unsigned)eD.y);
            a0 = __hfma2(wA, u2h2(hA.x), a0); a1 = __hfma2(wA, u2h2(hA.y), a1);
            a2 = __hfma2(wA, u2h2(hA.z), a2); a3 = __hfma2(wA, u2h2(hA.w), a3);
            a0 = __hfma2(wB, u2h2(hB.x), a0); a1 = __hfma2(wB, u2h2(hB.y), a1);
            a2 = __hfma2(wB, u2h2(hB.z), a2); a3 = __hfma2(wB, u2h2(hB.w), a3);
            a0 = __hfma2(wC, u2h2(hC.x), a0); a1 = __hfma2(wC, u2h2(hC.y), a1);
            a2 = __hfma2(wC, u2h2(hC.z), a2); a3 = __hfma2(wC, u2h2(hC.w), a3);
            a0 = __hfma2(wD, u2h2(hD.x), a0); a1 = __hfma2(wD, u2h2(hD.y), a1);
            a2 = __hfma2(wD, u2h2(hD.z), a2); a3 = __hfma2(wD, u2h2(hD.w), a3);
        }
        for (; i < e; i += 2) {
            int2 eA = g_csr[i];
            uint4 hA = hb[eA.x + sl];
            __half2 wA = u2h2((unsigned)eA.y);
            a0 = __hfma2(wA, u2h2(hA.x), a0);
            a1 = __hfma2(wA, u2h2(hA.y), a1);
            a2 = __hfma2(wA, u2h2(hA.z), a2);
            a3 = __hfma2(wA, u2h2(hA.w), a3);
        }
        // combine the two edge-parity groups
#define COMB(r) r = __hadd2(r, u2h2(__shfl_down_sync(0xffffffffu, *(unsigned*)&r, 16)))
        COMB(a0); COMB(a1); COMB(a2); COMB(a3);
#undef COMB

        if (hf == 0) {
            uint4 hs = hb[dst * 16 + sl];
            float2 s0 = __half22float2(u2h2(hs.x));
            float2 s1 = __half22float2(u2h2(hs.y));
            float2 s2 = __half22float2(u2h2(hs.z));
            float2 s3 = __half22float2(u2h2(hs.w));
            float2 f0 = __half22float2(a0);
            float2 f1 = __half22float2(a1);
            float2 f2 = __half22float2(a2);
            float2 f3 = __half22float2(a3);
            float4 bia = *(const float4*)(b1 + 8 * sl);
            float4 bib = *(const float4*)(b1 + 8 * sl + 4);
            float sn = g_selfn[dst];
            float c  = g_c[dst];
            float t0 = fmaf(sn, s0.x, bia.x) + f0.x;
            float t1 = fmaf(sn, s0.y, bia.y) + f0.y;
            float t2 = fmaf(sn, s1.x, bia.z) + f1.x;
            float t3 = fmaf(sn, s1.y, bia.w) + f1.y;
            float t4 = fmaf(sn, s2.x, bib.x) + f2.x;
            float t5 = fmaf(sn, s2.y, bib.y) + f2.y;
            float t6 = fmaf(sn, s3.x, bib.z) + f3.x;
            float t7 = fmaf(sn, s3.y, bib.w) + f3.y;
            vacc0.x = fmaf(c, fmaxf(t0, 0.f), vacc0.x);
            vacc0.y = fmaf(c, fmaxf(t1, 0.f), vacc0.y);
            vacc0.z = fmaf(c, fmaxf(t2, 0.f), vacc0.z);
            vacc0.w = fmaf(c, fmaxf(t3, 0.f), vacc0.w);
            vacc1.x = fmaf(c, fmaxf(t4, 0.f), vacc1.x);
            vacc1.y = fmaf(c, fmaxf(t5, 0.f), vacc1.y);
            vacc1.z = fmaf(c, fmaxf(t6, 0.f), vacc1.z);
            vacc1.w = fmaf(c, fmaxf(t7, 0.f), vacc1.w);
        }
    }
    if (hf == 0) {
        float* vb = g_v + b * ND + 8 * sl;
        atomicAdd(vb + 0, vacc0.x);
        atomicAdd(vb + 1, vacc0.y);
        atomicAdd(vb + 2, vacc0.z);
        atomicAdd(vb + 3, vacc0.w);
        atomicAdd(vb + 4, vacc1.x);
        atomicAdd(vb + 5, vacc1.y);
        atomicAdd(vb + 6, vacc1.z);
        atomicAdd(vb + 7, vacc1.w);
    }
}

// ---------------- final: split-k GEMV, out[b,:] = (v[b,:]/N) @ W2 + b2 ----------------
__global__ void __launch_bounds__(512)
k_final(const float* __restrict__ W2, const float* __restrict__ b2,
        float* __restrict__ out) {
    __shared__ float vs[ND];
    __shared__ float part[3][ND];
    int b = blockIdx.x;
    int tid = threadIdx.x;
    int q = tid >> 7, d = tid & 127;
    if (tid < ND) vs[tid] = g_v[b * ND + tid] * (1.0f / NN);
    __syncthreads();
    float acc = 0.f;
    int k0 = q * 32;
#pragma unroll
    for (int kk = 0; kk < 32; kk++) {
        int k = k0 + kk;
        acc = fmaf(vs[k], W2[k * ND + d], acc);
    }
    if (q > 0) part[q - 1][d] = acc;
    __syncthreads();
    if (q == 0)
        out[b * ND + d] = acc + part[0][d] + part[1][d] + part[2][d] + b2[d];
}

// ---------------- launch: gemm forked onto side stream, joined before agg ----------------
namespace {
struct LaunchCtx {
    cudaStream_t s2;
    cudaEvent_t evFork, evJoin;
    LaunchCtx() {
        cudaStreamCreateWithFlags(&s2, cudaStreamNonBlocking);
        cudaEventCreateWithFlags(&evFork, cudaEventDisableTiming);
        cudaEventCreateWithFlags(&evJoin, cudaEventDisableTiming);
    }
};
}

extern "C" void kernel_launch(void* const* d_in, const int* in_sizes, int n_in,
                              void* d_out, int out_size) {
    // one-time resource creation (same launch sequence every call)
    static LaunchCtx ctx;

    const float* gene = (const float*)d_in[0];
    const int*   esrc = (const int*)d_in[1];
    const int*   edst = (const int*)d_in[2];
    const float* W1   = (const float*)d_in[3];
    const float* b1   = (const float*)d_in[4];
    const float* W2   = (const float*)d_in[5];
    const float* b2   = (const float*)d_in[6];
    float* out = (float*)d_out;

    // fork: gemm (independent) runs on ctx.s2 concurrently with scandinv+scatter
    cudaEventRecord(ctx.evFork, 0);
    cudaStreamWaitEvent(ctx.s2, ctx.evFork, 0);

    k_scandinv<<<1, 1024>>>(edst);                             // 1
    k_scatter<<<(NE + 255) / 256, 256>>>(esrc, edst);          // 2
    k_gemm_mma<<<(NB * NN) / 128, 256, 0, ctx.s2>>>(gene, W1); // 3 (side stream)

    // join: agg needs both CSR (stream 0) and h1 (s2)
    cudaEventRecord(ctx.evJoin, ctx.s2);
    cudaStreamWaitEvent(0, ctx.evJoin, 0);

    dim3 agrid((NN + 4 * WCHUNK - 1) / (4 * WCHUNK), NB);      // 100 x 32
    k_agg<<<agrid, 128>>>(b1);                                 // 4  <- ncu profiles this
    k_final<<<NB, 512>>>(W2, b2, out);                         // 5
}

// round 15
// speedup vs baseline: 1.4365x; 1.4365x over previous
#include <cuda_runtime.h>
#include <cuda_fp16.h>
#include <cstdint>

#define NB 32
#define NN 2000
#define NE 64000
#define ND 128
#define WCHUNK 10

// ---------------- scratch ----------------
__device__ int    g_cursor[NN];
__device__ float  g_dinv[NN];
__device__ float  g_selfn[NN];
__device__ float  g_c[NN];
__device__ int    g_rs[NN + 1];
__device__ int2   g_csr[NE];            // (src*16 [uint4 units], w packed half2)
__device__ float  g_v[NB * ND];
__device__ __half g_h1[(size_t)NB * NN * ND];  // layer-1 output, fp16 (16.4 MB)

__device__ __forceinline__ __half2 u2h2(unsigned u) { return *reinterpret_cast<__half2*>(&u); }

// ---------------- prep: count(smem) + scan + dinv/selfn/c + zero, one block ----------------
__global__ void k_scandinv(const int* __restrict__ dst) {
    __shared__ int cnt[2048];
    __shared__ int s[2048];
    int t = threadIdx.x;                 // 1024 threads
    cnt[t] = 0; cnt[t + 1024] = 0;
    __syncthreads();
    for (int e = t; e < NE; e += 1024) atomicAdd(&cnt[dst[e]], 1);
    __syncthreads();
    for (int i = t; i < NN; i += 1024) {
        float di = rsqrtf((float)(cnt[i] + 1));
        g_dinv[i]  = di;
        float sn   = di * di;
        g_selfn[i] = sn;
        g_c[i]     = sn;
        g_cursor[i] = 0;
    }
    s[t] = cnt[t]; s[t + 1024] = cnt[t + 1024];
    __syncthreads();
    for (int off = 1; off < 2048; off <<= 1) {
        int v0 = (t >= off) ? s[t - off] : 0;
        int v1 = s[t + 1024 - off];
        __syncthreads();
        s[t] += v0;
        s[t + 1024] += v1;
        __syncthreads();
    }
    if (t == 0) g_rs[0] = 0;
    if (t < NN) g_rs[t + 1] = s[t];
    if (t + 1024 < NN) g_rs[t + 1025] = s[t + 1024];
    for (int i = t; i < NB * ND; i += 1024) g_v[i] = 0.f;
}

__global__ void k_scatter(const int* __restrict__ src, const int* __restrict__ dst) {
    int e = blockIdx.x * blockDim.x + threadIdx.x;
    if (e < NE) {
        int dd = dst[e], ss = src[e];
        float w = g_dinv[ss] * g_dinv[dd];
        int p = g_rs[dd] + atomicAdd(&g_cursor[dd], 1);
        __half2 hw = __floats2half2_rn(w, w);
        g_csr[p] = make_int2(ss * 16, *reinterpret_cast<int*>(&hw));
        atomicAdd(&g_c[ss], w);
    }
}

// ---------------- GEMM1 via mma.sync (HMMA): h1 = X @ W1, fp16 in, fp32 acc ----------------
#define AS_STRIDE 132

__device__ __forceinline__ void mma16816(float* c, const uint32_t* a, const uint32_t* b) {
    asm volatile(
        "mma.sync.aligned.m16n8k16.row.col.f32.f16.f16.f32 "
        "{%0,%1,%2,%3}, {%4,%5,%6,%7}, {%8,%9}, {%0,%1,%2,%3};"
        : "+f"(c[0]), "+f"(c[1]), "+f"(c[2]), "+f"(c[3])
        : "r"(a[0]), "r"(a[1]), "r"(a[2]), "r"(a[3]), "r"(b[0]), "r"(b[1]));
}

__global__ void __launch_bounds__(256, 1)
k_gemm_mma(const float* __restrict__ X, const float* __restrict__ W1) {
    __shared__ __half As[128 * AS_STRIDE];
    __shared__ __half Bs[128 * AS_STRIDE];   // Bs[n][k] = W1[k][n]
    int tid = threadIdx.x;
    int wid = tid >> 5, lane = tid & 31;
    size_t row0 = (size_t)blockIdx.x * 128;

#pragma unroll
    for (int i = 0; i < 32; i++) {
        int idx = tid + i * 256;
        int row = idx >> 6, c2 = idx & 63;
        float2 xv = *(const float2*)(X + (row0 + row) * ND + c2 * 2);
        *(__half2*)(As + row * AS_STRIDE + c2 * 2) = __floats2half2_rn(xv.x, xv.y);
    }
#pragma unroll
    for (int i = 0; i < 64; i++) {
        int idx = tid + i * 256;
        int n = idx & 127, k = idx >> 7;
        Bs[n * AS_STRIDE + k] = __float2half(W1[idx]);
    }
    __syncthreads();

    int wr = (wid & 3) * 32;
    int wc = (wid >> 2) * 64;
    int grp = lane >> 2;
    int tig = lane & 3;

    float acc[2][8][4];
#pragma unroll
    for (int mt = 0; mt < 2; mt++)
#pragma unroll
        for (int nt = 0; nt < 8; nt++)
#pragma unroll
            for (int q = 0; q < 4; q++) acc[mt][nt][q] = 0.f;

#pragma unroll
    for (int kc = 0; kc < 8; kc++) {
        int k0 = kc * 16;
        uint32_t a[2][4];
#pragma unroll
        for (int mt = 0; mt < 2; mt++) {
            const __half* base = As + (wr + mt * 16) * AS_STRIDE + k0;
            a[mt][0] = *(const uint32_t*)(base + grp * AS_STRIDE + tig * 2);
            a[mt][1] = *(const uint32_t*)(base + (grp + 8) * AS_STRIDE + tig * 2);
            a[mt][2] = *(const uint32_t*)(base + grp * AS_STRIDE + tig * 2 + 8);
            a[mt][3] = *(const uint32_t*)(base + (grp + 8) * AS_STRIDE + tig * 2 + 8);
        }
#pragma unroll
        for (int nt = 0; nt < 8; nt++) {
            uint32_t b[2];
            const __half* bb = Bs + (wc + nt * 8 + grp) * AS_STRIDE + k0;
            b[0] = *(const uint32_t*)(bb + tig * 2);
            b[1] = *(const uint32_t*)(bb + tig * 2 + 8);
            mma16816(acc[0][nt], a[0], b);
            mma16816(acc[1][nt], a[1], b);
        }
    }

#pragma unroll
    for (int mt = 0; mt < 2; mt++) {
        size_t r0 = row0 + wr + mt * 16 + grp;
#pragma unroll
        for (int nt = 0; nt < 8; nt++) {
            int col = wc + nt * 8 + tig * 2;
            __half2 lo = __floats2half2_rn(acc[mt][nt][0], acc[mt][nt][1]);
            __half2 hi = __floats2half2_rn(acc[mt][nt][2], acc[mt][nt][3]);
            *(__half2*)(g_h1 + r0 * ND + col)       = lo;
            *(__half2*)(g_h1 + (r0 + 8) * ND + col) = hi;
        }
    }
}

// ---------------- agg: 2 edges/warp-iter (parity groups), unroll 4, HFMA2 ----------------
// block = 128 threads (4 warps); each warp: WCHUNK dsts; 16 lanes cover 128 dims
__global__ void __launch_bounds__(128)
k_agg(const float* __restrict__ b1) {
    int warp = threadIdx.x >> 5, lane = threadIdx.x & 31;
    int hf = lane >> 4;                   // edge-parity group
    int sl = lane & 15;                   // dims 8*sl .. 8*sl+7
    int b = blockIdx.y;
    int dst0 = (blockIdx.x * 4 + warp) * WCHUNK;
    int dst1 = min(dst0 + WCHUNK, NN);
    const uint4* __restrict__ hb = (const uint4*)(g_h1 + (size_t)b * NN * ND);

    float4 vacc0 = make_float4(0.f, 0.f, 0.f, 0.f);
    float4 vacc1 = make_float4(0.f, 0.f, 0.f, 0.f);

    for (int dst = dst0; dst < dst1; ++dst) {
        int s = g_rs[dst], e = g_rs[dst + 1];
        __half2 a0 = __floats2half2_rn(0.f, 0.f), a1 = a0, a2 = a0, a3 = a0;
        int i = s + hf;
        // unroll 4: group handles edges i, i+2, i+4, i+6 -> 4 LDG.128 in flight
        for (; i + 6 < e; i += 8) {
            int2 eA = g_csr[i],     eB = g_csr[i + 2];
            int2 eC = g_csr[i + 4], eD = g_csr[i + 6];
            uint4 hA = hb[eA.x + sl];
            uint4 hB = hb[eB.x + sl];
            uint4 hC = hb[eC.x + sl];
            uint4 hD = hb[eD.x + sl];
            __half2 wA = u2h2((unsigned)eA.y), wB = u2h2((unsigned)eB.y);
            __half2 wC = u2h2((unsigned)eC.y), wD = u2h2((unsigned)eD.y);
            a0 = __hfma2(wA, u2h2(hA.x), a0); a1 = __hfma2(wA, u2h2(hA.y), a1);
            a2 = __hfma2(wA, u2h2(hA.z), a2); a3 = __hfma2(wA, u2h2(hA.w), a3);
            a0 = __hfma2(wB, u2h2(hB.x), a0); a1 = __hfma2(wB, u2h2(hB.y), a1);
            a2 = __hfma2(wB, u2h2(hB.z), a2); a3 = __hfma2(wB, u2h2(hB.w), a3);
            a0 = __hfma2(wC, u2h2(hC.x), a0); a1 = __hfma2(wC, u2h2(hC.y), a1);
            a2 = __hfma2(wC, u2h2(hC.z), a2); a3 = __hfma2(wC, u2h2(hC.w), a3);
            a0 = __hfma2(wD, u2h2(hD.x), a0); a1 = __hfma2(wD, u2h2(hD.y), a1);
            a2 = __hfma2(wD, u2h2(hD.z), a2); a3 = __hfma2(wD, u2h2(hD.w), a3);
        }
        for (; i < e; i += 2) {
            int2 eA = g_csr[i];
            uint4 hA = hb[eA.x + sl];
            __half2 wA = u2h2((unsigned)eA.y);
            a0 = __hfma2(wA, u2h2(hA.x), a0);
            a1 = __hfma2(wA, u2h2(hA.y), a1);
            a2 = __hfma2(wA, u2h2(hA.z), a2);
            a3 = __hfma2(wA, u2h2(hA.w), a3);
        }
        // combine the two edge-parity groups
#define COMB(r) r = __hadd2(r, u2h2(__shfl_down_sync(0xffffffffu, *(unsigned*)&r, 16)))
        COMB(a0); COMB(a1); COMB(a2); COMB(a3);
#undef COMB

        if (hf == 0) {
            uint4 hs = hb[dst * 16 + sl];
            float2 s0 = __half22float2(u2h2(hs.x));
            float2 s1 = __half22float2(u2h2(hs.y));
            float2 s2 = __half22float2(u2h2(hs.z));
            float2 s3 = __half22float2(u2h2(hs.w));
            float2 f0 = __half22float2(a0);
            float2 f1 = __half22float2(a1);
            float2 f2 = __half22float2(a2);
            float2 f3 = __half22float2(a3);
            float4 bia = *(const float4*)(b1 + 8 * sl);
            float4 bib = *(const float4*)(b1 + 8 * sl + 4);
            float sn = g_selfn[dst];
            float c  = g_c[dst];
            float t0 = fmaf(sn, s0.x, bia.x) + f0.x;
            float t1 = fmaf(sn, s0.y, bia.y) + f0.y;
            float t2 = fmaf(sn, s1.x, bia.z) + f1.x;
            float t3 = fmaf(sn, s1.y, bia.w) + f1.y;
            float t4 = fmaf(sn, s2.x, bib.x) + f2.x;
            float t5 = fmaf(sn, s2.y, bib.y) + f2.y;
            float t6 = fmaf(sn, s3.x, bib.z) + f3.x;
            float t7 = fmaf(sn, s3.y, bib.w) + f3.y;
            vacc0.x = fmaf(c, fmaxf(t0, 0.f), vacc0.x);
            vacc0.y = fmaf(c, fmaxf(t1, 0.f), vacc0.y);
            vacc0.z = fmaf(c, fmaxf(t2, 0.f), vacc0.z);
            vacc0.w = fmaf(c, fmaxf(t3, 0.f), vacc0.w);
            vacc1.x = fmaf(c, fmaxf(t4, 0.f), vacc1.x);
            vacc1.y = fmaf(c, fmaxf(t5, 0.f), vacc1.y);
            vacc1.z = fmaf(c, fmaxf(t6, 0.f), vacc1.z);
            vacc1.w = fmaf(c, fmaxf(t7, 0.f), vacc1.w);
        }
    }
    if (hf == 0) {
        float* vb = g_v + b * ND + 8 * sl;
        atomicAdd(vb + 0, vacc0.x);
        atomicAdd(vb + 1, vacc0.y);
        atomicAdd(vb + 2, vacc0.z);
        atomicAdd(vb + 3, vacc0.w);
        atomicAdd(vb + 4, vacc1.x);
        atomicAdd(vb + 5, vacc1.y);
        atomicAdd(vb + 6, vacc1.z);
        atomicAdd(vb + 7, vacc1.w);
    }
}

// ---------------- final: split-k GEMV, out[b,:] = (v[b,:]/N) @ W2 + b2 ----------------
__global__ void __launch_bounds__(512)
k_final(const float* __restrict__ W2, const float* __restrict__ b2,
        float* __restrict__ out) {
    __shared__ float vs[ND];
    __shared__ float part[3][ND];
    int b = blockIdx.x;
    int tid = threadIdx.x;
    int q = tid >> 7, d = tid & 127;
    if (tid < ND) vs[tid] = g_v[b * ND + tid] * (1.0f / NN);
    __syncthreads();
    float acc = 0.f;
    int k0 = q * 32;
#pragma unroll
    for (int kk = 0; kk < 32; kk++) {
        int k = k0 + kk;
        acc = fmaf(vs[k], W2[k * ND + d], acc);
    }
    if (q > 0) part[q - 1][d] = acc;
    __syncthreads();
    if (q == 0)
        out[b * ND + d] = acc + part[0][d] + part[1][d] + part[2][d] + b2[d];
}

// ---------------- launch: gemm forked onto side stream, joined before agg ----------------
namespace {
struct LaunchCtx {
    cudaStream_t s2;
    cudaEvent_t evFork, evJoin;
    LaunchCtx() {
        cudaStreamCreateWithFlags(&s2, cudaStreamNonBlocking);
        cudaEventCreateWithFlags(&evFork, cudaEventDisableTiming);
        cudaEventCreateWithFlags(&evJoin, cudaEventDisableTiming);
    }
};
}

extern "C" void kernel_launch(void* const* d_in, const int* in_sizes, int n_in,
                              void* d_out, int out_size) {
    static LaunchCtx ctx;

    const float* gene = (const float*)d_in[0];
    const int*   esrc = (const int*)d_in[1];
    const int*   edst = (const int*)d_in[2];
    const float* W1   = (const float*)d_in[3];
    const float* b1   = (const float*)d_in[4];
    const float* W2   = (const float*)d_in[5];
    const float* b2   = (const float*)d_in[6];
    float* out = (float*)d_out;

    // fork: gemm (independent) runs on ctx.s2 concurrently with scandinv+scatter
    cudaEventRecord(ctx.evFork, 0);
    cudaStreamWaitEvent(ctx.s2, ctx.evFork, 0);

    k_scandinv<<<1, 1024>>>(edst);                             // 1
    k_scatter<<<(NE + 255) / 256, 256>>>(esrc, edst);          // 2
    k_gemm_mma<<<(NB * NN) / 128, 256, 0, ctx.s2>>>(gene, W1); // 3 (side stream)

    // join: agg needs both CSR (stream 0) and h1 (s2)
    cudaEventRecord(ctx.evJoin, ctx.s2);
    cudaStreamWaitEvent(0, ctx.evJoin, 0);

    dim3 agrid((NN + 4 * WCHUNK - 1) / (4 * WCHUNK), NB);      // 50 x 32
    k_agg<<<agrid, 128>>>(b1);                                 // 4  <- ncu profiles this
    k_final<<<NB, 512>>>(W2, b2, out);                         // 5
}